// round 9
// baseline (speedup 1.0000x reference)
#include <cuda_runtime.h>
#include <cuda_fp16.h>
#include <mma.h>
#include <cstddef>
#include <cstdint>

using namespace nvcuda;

// Problem constants
#define BATCH 128
#define HH 14
#define WW 14
#define CC 768
#define NHEAD 12
#define HDIM 64
#define HWSZ 196          // 14*14
#define C3 2304           // 3*C
#define MROWS 25088       // BATCH*HWSZ
#define NHEADS_TOTAL 1536 // BATCH*NHEAD

typedef unsigned long long u64;

// Scratch buffers (device globals: no allocation allowed)
__device__ float  g_qkv[(size_t)MROWS * C3];  // qkv GEMM out (fp32)
__device__ __half g_att[(size_t)MROWS * CC];  // attention out (fp16)
__device__ __half g_x[(size_t)MROWS * CC];    // x (fp16)
__device__ __half g_wqkv[(size_t)CC * C3];    // w_qkv (fp16)
__device__ __half g_wproj[(size_t)CC * CC];   // w_proj (fp16)

// ---------------------------------------------------------------------------
// helpers
// ---------------------------------------------------------------------------
__global__ void to_half_kernel(const float* __restrict__ in,
                               __half* __restrict__ out, int n4)
{
    int i = blockIdx.x * blockDim.x + threadIdx.x;
    if (i < n4) {
        float4 v = ((const float4*)in)[i];
        __half2 a = __floats2half2_rn(v.x, v.y);
        __half2 b = __floats2half2_rn(v.z, v.w);
        uint2 pk;
        pk.x = *(uint32_t*)&a;
        pk.y = *(uint32_t*)&b;
        ((uint2*)out)[i] = pk;
    }
}

// packed f32x2 ops (Blackwell)
__device__ __forceinline__ u64 fma2(u64 a, u64 b, u64 c) {
    u64 d;
    asm("fma.rn.f32x2 %0, %1, %2, %3;" : "=l"(d) : "l"(a), "l"(b), "l"(c));
    return d;
}
__device__ __forceinline__ u64 pack2(float lo, float hi) {
    u64 d;
    asm("mov.b64 %0, {%1, %2};" : "=l"(d) : "f"(lo), "f"(hi));
    return d;
}
__device__ __forceinline__ float hsum2(u64 v) {
    float a, b;
    asm("mov.b64 {%0, %1}, %2;" : "=f"(a), "=f"(b) : "l"(v));
    return a + b;
}

__device__ __forceinline__ void cpa16(void* s, const void* g) {
    uint32_t sa = (uint32_t)__cvta_generic_to_shared(s);
    asm volatile("cp.async.cg.shared.global [%0], [%1], 16;\n" ::"r"(sa), "l"(g));
}
__device__ __forceinline__ void cpa_commit() {
    asm volatile("cp.async.commit_group;\n" ::);
}
template <int N>
__device__ __forceinline__ void cpa_wait() {
    asm volatile("cp.async.wait_group %0;\n" ::"n"(N));
}

// ---------------------------------------------------------------------------
// Pipelined fp16 GEMM: C(fp32) = A(MxK,f16) @ B(KxN,f16) + bias(fp32)
// BM=BN=128, BK=64, wmma m16n16k16, 2-stage cp.async, 256 thr, 2 CTA/SM.
// ---------------------------------------------------------------------------
#define BM 128
#define BN 128
#define BK 64
#define BSTR 136   // halves per B row: 128 + 8 pad
#define ASTRH 72   // halves per A row: 64 + 8 pad

#define GEMM_SMEM_BYTES ((2 * BM * ASTRH + 2 * BK * BSTR) * 2 + 16 * BSTR * 4)

__device__ __forceinline__ void gemm_body(
    const __half* __restrict__ A, const __half* __restrict__ Bm,
    const float* __restrict__ bias, float* __restrict__ Cout,
    int M, int N, int K)
{
    extern __shared__ char smraw[];
    __half* As = (__half*)smraw;                       // 2 x BM x ASTRH
    __half* Bs = As + 2 * BM * ASTRH;                  // 2 x BK x BSTR
    float* biasT = (float*)(Bs + 2 * BK * BSTR);       // 16 x BSTR fp32

    const int tid = threadIdx.x;
    const int m0 = blockIdx.y * BM;
    const int n0 = blockIdx.x * BN;

    for (int i = tid; i < 16 * BN; i += 256) {
        int rr = i >> 7, cc = i & 127;
        biasT[rr * BSTR + cc] = bias[n0 + cc];
    }
    __syncthreads();

    const int w  = tid >> 5;
    const int wm = w >> 2;
    const int wn = w & 3;

    wmma::fragment<wmma::accumulator, 16, 16, 16, float> acc[4][2];
#pragma unroll
    for (int i = 0; i < 4; i++)
#pragma unroll
        for (int j = 0; j < 2; j++)
            wmma::load_matrix_sync(acc[i][j], &biasT[wn * 32 + j * 16], BSTR,
                                   wmma::mem_row_major);

    const int arow = tid >> 3, ac8 = (tid & 7) * 8;
    const int brow = tid >> 4, bc8 = (tid & 15) * 8;

    const int T = K / BK;

    {
        const __half* ag = &A[(size_t)(m0 + arow) * K + ac8];
        const __half* bg = &Bm[(size_t)brow * N + n0 + bc8];
#pragma unroll
        for (int p = 0; p < 4; p++)
            cpa16(&As[(arow + p * 32) * ASTRH + ac8], ag + (size_t)(p * 32) * K);
#pragma unroll
        for (int p = 0; p < 4; p++)
            cpa16(&Bs[(brow + p * 16) * BSTR + bc8], bg + (size_t)(p * 16) * N);
        cpa_commit();
    }

    for (int t = 0; t < T; t++) {
        if (t + 1 < T) {
            const int st = (t + 1) & 1;
            const int kt = (t + 1) * BK;
            const __half* ag = &A[(size_t)(m0 + arow) * K + kt + ac8];
            const __half* bg = &Bm[(size_t)(kt + brow) * N + n0 + bc8];
            __half* asd = &As[st * BM * ASTRH];
            __half* bsd = &Bs[st * BK * BSTR];
#pragma unroll
            for (int p = 0; p < 4; p++)
                cpa16(&asd[(arow + p * 32) * ASTRH + ac8], ag + (size_t)(p * 32) * K);
#pragma unroll
            for (int p = 0; p < 4; p++)
                cpa16(&bsd[(brow + p * 16) * BSTR + bc8], bg + (size_t)(p * 16) * N);
            cpa_commit();
            cpa_wait<1>();
        } else {
            cpa_wait<0>();
        }
        __syncthreads();

        const __half* asrc = &As[(t & 1) * BM * ASTRH];
        const __half* bsrc = &Bs[(t & 1) * BK * BSTR];

#pragma unroll
        for (int kk = 0; kk < BK; kk += 16) {
            wmma::fragment<wmma::matrix_a, 16, 16, 16, __half, wmma::row_major> af[4];
            wmma::fragment<wmma::matrix_b, 16, 16, 16, __half, wmma::row_major> bf[2];
#pragma unroll
            for (int i = 0; i < 4; i++)
                wmma::load_matrix_sync(af[i], &asrc[(wm * 64 + i * 16) * ASTRH + kk], ASTRH);
#pragma unroll
            for (int j = 0; j < 2; j++)
                wmma::load_matrix_sync(bf[j], &bsrc[kk * BSTR + wn * 32 + j * 16], BSTR);
#pragma unroll
            for (int i = 0; i < 4; i++)
#pragma unroll
                for (int j = 0; j < 2; j++)
                    wmma::mma_sync(acc[i][j], af[i], bf[j], acc[i][j]);
        }
        __syncthreads();
    }

#pragma unroll
    for (int i = 0; i < 4; i++)
#pragma unroll
        for (int j = 0; j < 2; j++)
            wmma::store_matrix_sync(
                Cout + (size_t)(m0 + wm * 64 + i * 16) * N + n0 + wn * 32 + j * 16,
                acc[i][j], N, wmma::mem_row_major);
}

__global__ __launch_bounds__(256, 2) void gemm_qkv_k(const float* __restrict__ bias)
{
    gemm_body(g_x, g_wqkv, bias, g_qkv, MROWS, C3, CC);
}

__global__ __launch_bounds__(256, 2) void gemm_proj_k(
    const float* __restrict__ bias, float* __restrict__ C)
{
    gemm_body(g_att, g_wproj, bias, C, MROWS, CC, CC);
}

// ---------------------------------------------------------------------------
// Fused attention, packed f32x2 FMA, 512 threads (16 warps) per CTA.
// Rel-pos tables appended to K as extra "key" rows: rows 224..250 = Rh,
// 256..282 = Rw, so rel dots use the coalesced QK^T machinery instead of a
// scattered per-lane dot phase (which was the smem-crossbar hotspot).
// No softmax max-subtraction (logits bounded). Output fp16 for proj GEMM.
// ---------------------------------------------------------------------------
#define KSTR 68
#define NWARP 16
#define NTHR (NWARP * 32)

#define SM_K   (288 * KSTR)          // K rows 0..195, pads, Rh 224.., Rw 256..
#define SM_V   (196 * KSTR)
#define SM_Q   (NWARP * 4 * KSTR)
#define SM_P   (NWARP * 4 * 200)
#define SM_REL (NWARP * 4 * 64)      // per warp: 4 rows x (32 relh + 32 relw)
#define ATTN_SMEM_FLOATS (SM_K + SM_V + SM_Q + SM_P + SM_REL)
#define ATTN_SMEM_BYTES (ATTN_SMEM_FLOATS * 4)

__global__ __launch_bounds__(NTHR) void attn_kernel(
    const float* __restrict__ rph, const float* __restrict__ rpw)
{
    extern __shared__ float sm[];
    float* kS  = sm;
    float* vS  = kS + SM_K;
    float* qsm = vS + SM_V;
    float* pbf = qsm + SM_Q;
    float* rlb = pbf + SM_P;

    const int tid  = threadIdx.x;
    const int head = blockIdx.x;
    const int b = head / NHEAD;
    const int h = head % NHEAD;

    const float* gbase = g_qkv + (size_t)b * HWSZ * C3 + h * HDIM;

    // Stage K, V
    for (int i = tid; i < HWSZ * HDIM; i += NTHR) {
        int j = i >> 6, d = i & 63;
        const float* p = gbase + (size_t)j * C3 + d;
        kS[j * KSTR + d] = p[768];
        vS[j * KSTR + d] = p[1536];
    }
    // Zero pad rows: 196..223, 251..255, 283..287
    for (int i = tid; i < 28 * KSTR; i += NTHR) kS[196 * KSTR + i] = 0.f;
    for (int i = tid; i < 5 * KSTR; i += NTHR) {
        kS[251 * KSTR + i] = 0.f;
        kS[283 * KSTR + i] = 0.f;
    }
    // Rel tables as extra key rows
    for (int i = tid; i < 27 * HDIM; i += NTHR) {
        int r = i >> 6, d = i & 63;
        kS[(224 + r) * KSTR + d] = rph[i];
        kS[(256 + r) * KSTR + d] = rpw[i];
    }
    __syncthreads();

    const int wid = tid >> 5, lane = tid & 31;
    float* qw = qsm + wid * 4 * KSTR;
    float* pw = pbf + wid * 800;
    float* rb = rlb + wid * 256;

    for (int g = wid; g < 49; g += NWARP) {
        const int r0 = g * 4;

        for (int i = lane; i < 4 * HDIM; i += 32) {
            int rr = i >> 6, d = i & 63;
            qw[rr * KSTR + d] = gbase[(size_t)(r0 + rr) * C3 + d];
        }
        __syncwarp();

        // QK^T main keys: packed along d
        u64 acc2[4][7];
#pragma unroll
        for (int rr = 0; rr < 4; rr++)
#pragma unroll
            for (int jj = 0; jj < 7; jj++) acc2[rr][jj] = 0ull;

#pragma unroll 4
        for (int d0 = 0; d0 < 64; d0 += 4) {
            ulonglong2 qv[4];
#pragma unroll
            for (int rr = 0; rr < 4; rr++)
                qv[rr] = *(const ulonglong2*)(qw + rr * KSTR + d0);
#pragma unroll
            for (int jj = 0; jj < 7; jj++) {
                int j = lane + jj * 32;  // pad rows (>=196) are zero
                ulonglong2 kv = *(const ulonglong2*)(kS + j * KSTR + d0);
#pragma unroll
                for (int rr = 0; rr < 4; rr++) {
                    acc2[rr][jj] = fma2(kv.x, qv[rr].x, acc2[rr][jj]);
                    acc2[rr][jj] = fma2(kv.y, qv[rr].y, acc2[rr][jj]);
                }
            }
        }

        // Rel-pos dots via the same coalesced pattern (rows 224+lane, 256+lane)
        {
            u64 ar[4][2];
#pragma unroll
            for (int rr = 0; rr < 4; rr++) { ar[rr][0] = 0ull; ar[rr][1] = 0ull; }
#pragma unroll 4
            for (int d0 = 0; d0 < 64; d0 += 4) {
                ulonglong2 qv[4];
#pragma unroll
                for (int rr = 0; rr < 4; rr++)
                    qv[rr] = *(const ulonglong2*)(qw + rr * KSTR + d0);
                ulonglong2 hv = *(const ulonglong2*)(kS + (224 + lane) * KSTR + d0);
                ulonglong2 wv = *(const ulonglong2*)(kS + (256 + lane) * KSTR + d0);
#pragma unroll
                for (int rr = 0; rr < 4; rr++) {
                    ar[rr][0] = fma2(hv.x, qv[rr].x, ar[rr][0]);
                    ar[rr][0] = fma2(hv.y, qv[rr].y, ar[rr][0]);
                    ar[rr][1] = fma2(wv.x, qv[rr].x, ar[rr][1]);
                    ar[rr][1] = fma2(wv.y, qv[rr].y, ar[rr][1]);
                }
            }
            if (lane < 27) {
#pragma unroll
                for (int rr = 0; rr < 4; rr++) {
                    rb[rr * 64 + lane]      = hsum2(ar[rr][0]);  // q . Rh[lane]
                    rb[rr * 64 + 32 + lane] = hsum2(ar[rr][1]);  // q . Rw[lane]
                }
            }
        }
        __syncwarp();

        // softmax without max-subtraction (logits bounded)
        float inv[4];
#pragma unroll
        for (int rr = 0; rr < 4; rr++) {
            const int r = r0 + rr;
            const int hq = r / 14, wq = r % 14;
            const float* rbh = rb + rr * 64 + hq + 13;       // index - j/14
            const float* rbw = rb + rr * 64 + 32 + wq + 13;  // index - j%14
            float lsum = 0.f;
#pragma unroll
            for (int jj = 0; jj < 7; jj++) {
                int j = lane + jj * 32;
                if (j < HWSZ) {
                    float s = hsum2(acc2[rr][jj]) * 0.125f
                            + rbh[-(j / 14)] + rbw[-(j % 14)];
                    float e = __expf(s);
                    pw[rr * 200 + j] = e;
                    lsum += e;
                }
            }
#pragma unroll
            for (int o = 16; o > 0; o >>= 1)
                lsum += __shfl_xor_sync(0xffffffffu, lsum, o);
            inv[rr] = 1.f / lsum;
        }
        __syncwarp();

        // P @ V: packed along key pairs
        u64 o20[4] = {0ull, 0ull, 0ull, 0ull};
        u64 o21[4] = {0ull, 0ull, 0ull, 0ull};
#pragma unroll 2
        for (int j = 0; j < HWSZ; j += 2) {
            float2 va = *(const float2*)(vS + j * KSTR + 2 * lane);
            float2 vb = *(const float2*)(vS + (j + 1) * KSTR + 2 * lane);
            u64 vx = pack2(va.x, vb.x);
            u64 vy = pack2(va.y, vb.y);
#pragma unroll
            for (int rr = 0; rr < 4; rr++) {
                u64 pp = *(const u64*)(pw + rr * 200 + j);
                o20[rr] = fma2(pp, vx, o20[rr]);
                o21[rr] = fma2(pp, vy, o21[rr]);
            }
        }

        __half* gout = g_att + ((size_t)b * HWSZ + r0) * CC + h * HDIM;
#pragma unroll
        for (int rr = 0; rr < 4; rr++) {
            __half2 res = __floats2half2_rn(hsum2(o20[rr]) * inv[rr],
                                            hsum2(o21[rr]) * inv[rr]);
            *(__half2*)(gout + (size_t)rr * CC + 2 * lane) = res;
        }
        __syncwarp();
    }
}

// ---------------------------------------------------------------------------
extern "C" void kernel_launch(void* const* d_in, const int* in_sizes, int n_in,
                              void* d_out, int out_size)
{
    const float* x      = (const float*)d_in[0]; // (25088, 768)
    const float* w_qkv  = (const float*)d_in[1]; // (768, 2304)
    const float* b_qkv  = (const float*)d_in[2]; // (2304,)
    const float* rph    = (const float*)d_in[3]; // (27, 64)
    const float* rpw    = (const float*)d_in[4]; // (27, 64)
    const float* w_proj = (const float*)d_in[5]; // (768, 768)
    const float* b_proj = (const float*)d_in[6]; // (768,)
    float* out = (float*)d_out;                  // (25088, 768)

    __half *d_x, *d_wqkv, *d_wproj;
    cudaGetSymbolAddress((void**)&d_x, g_x);
    cudaGetSymbolAddress((void**)&d_wqkv, g_wqkv);
    cudaGetSymbolAddress((void**)&d_wproj, g_wproj);

    cudaFuncSetAttribute(gemm_qkv_k,
                         cudaFuncAttributeMaxDynamicSharedMemorySize,
                         GEMM_SMEM_BYTES);
    cudaFuncSetAttribute(gemm_proj_k,
                         cudaFuncAttributeMaxDynamicSharedMemorySize,
                         GEMM_SMEM_BYTES);
    cudaFuncSetAttribute(attn_kernel,
                         cudaFuncAttributeMaxDynamicSharedMemorySize,
                         ATTN_SMEM_BYTES);

    // Convert GEMM inputs to fp16
    {
        int n4 = MROWS * CC / 4;
        to_half_kernel<<<(n4 + 255) / 256, 256>>>(x, d_x, n4);
        n4 = CC * C3 / 4;
        to_half_kernel<<<(n4 + 255) / 256, 256>>>(w_qkv, d_wqkv, n4);
        n4 = CC * CC / 4;
        to_half_kernel<<<(n4 + 255) / 256, 256>>>(w_proj, d_wproj, n4);
    }

    dim3 g1(C3 / BN, MROWS / BM);   // 18 x 196
    gemm_qkv_k<<<g1, 256, GEMM_SMEM_BYTES>>>(b_qkv);

    attn_kernel<<<NHEADS_TOTAL, NTHR, ATTN_SMEM_BYTES>>>(rph, rpw);

    dim3 g2(CC / BN, MROWS / BM);   // 6 x 196
    gemm_proj_k<<<g2, 256, GEMM_SMEM_BYTES>>>(b_proj, out);
}

// round 10
// speedup vs baseline: 1.0195x; 1.0195x over previous
#include <cuda_runtime.h>
#include <cuda_fp16.h>
#include <mma.h>
#include <cstddef>
#include <cstdint>

using namespace nvcuda;

// Problem constants
#define BATCH 128
#define HH 14
#define WW 14
#define CC 768
#define NHEAD 12
#define HDIM 64
#define HWSZ 196          // 14*14
#define C3 2304           // 3*C
#define MROWS 25088       // BATCH*HWSZ
#define NHEADS_TOTAL 1536 // BATCH*NHEAD

typedef unsigned long long u64;

#define LOG2E 1.442695040888963f
#define QK_SCALE_LOG2 0.180336880111120f  // 0.125 * log2(e)

// Scratch buffers (device globals: no allocation allowed)
__device__ float  g_qkv[(size_t)MROWS * C3];  // qkv GEMM out (fp32)
__device__ __half g_att[(size_t)MROWS * CC];  // attention out (fp16)
__device__ __half g_x[(size_t)MROWS * CC];    // x (fp16)
__device__ __half g_wqkv[(size_t)CC * C3];    // w_qkv (fp16)
__device__ __half g_wproj[(size_t)CC * CC];   // w_proj (fp16)

// ---------------------------------------------------------------------------
// helpers
// ---------------------------------------------------------------------------
__global__ void to_half_kernel(const float* __restrict__ in,
                               __half* __restrict__ out, int n4)
{
    int i = blockIdx.x * blockDim.x + threadIdx.x;
    if (i < n4) {
        float4 v = ((const float4*)in)[i];
        __half2 a = __floats2half2_rn(v.x, v.y);
        __half2 b = __floats2half2_rn(v.z, v.w);
        uint2 pk;
        pk.x = *(uint32_t*)&a;
        pk.y = *(uint32_t*)&b;
        ((uint2*)out)[i] = pk;
    }
}

// packed f32x2 ops (Blackwell)
__device__ __forceinline__ u64 fma2(u64 a, u64 b, u64 c) {
    u64 d;
    asm("fma.rn.f32x2 %0, %1, %2, %3;" : "=l"(d) : "l"(a), "l"(b), "l"(c));
    return d;
}
__device__ __forceinline__ u64 pack2(float lo, float hi) {
    u64 d;
    asm("mov.b64 %0, {%1, %2};" : "=l"(d) : "f"(lo), "f"(hi));
    return d;
}
__device__ __forceinline__ float hsum2(u64 v) {
    float a, b;
    asm("mov.b64 {%0, %1}, %2;" : "=f"(a), "=f"(b) : "l"(v));
    return a + b;
}

// Packed 2^x for two fp32 args via f16x2 MUFU (1 EX2 for 2 values).
__device__ __forceinline__ float2 exp2_2(float a, float b) {
    uint32_t h, e;
    asm("cvt.rn.f16x2.f32 %0, %1, %2;" : "=r"(h) : "f"(b), "f"(a)); // hi=b, lo=a
    asm("ex2.approx.f16x2 %0, %1;" : "=r"(e) : "r"(h));
    float2 r;
    asm("{.reg .f16 lo, hi;\n\t"
        "mov.b32 {lo, hi}, %2;\n\t"
        "cvt.f32.f16 %0, lo;\n\t"
        "cvt.f32.f16 %1, hi;}"
        : "=f"(r.x), "=f"(r.y) : "r"(e));
    return r;
}

__device__ __forceinline__ void cpa16(void* s, const void* g) {
    uint32_t sa = (uint32_t)__cvta_generic_to_shared(s);
    asm volatile("cp.async.cg.shared.global [%0], [%1], 16;\n" ::"r"(sa), "l"(g));
}
__device__ __forceinline__ void cpa_commit() {
    asm volatile("cp.async.commit_group;\n" ::);
}
template <int N>
__device__ __forceinline__ void cpa_wait() {
    asm volatile("cp.async.wait_group %0;\n" ::"n"(N));
}

// ---------------------------------------------------------------------------
// Pipelined fp16 GEMM: C(fp32) = A(MxK,f16) @ B(KxN,f16) + bias(fp32)
// BM=BN=128, BK=64, wmma m16n16k16, 2-stage cp.async, 256 thr, 2 CTA/SM.
// ---------------------------------------------------------------------------
#define BM 128
#define BN 128
#define BK 64
#define BSTR 136   // halves per B row: 128 + 8 pad
#define ASTRH 72   // halves per A row: 64 + 8 pad

#define GEMM_SMEM_BYTES ((2 * BM * ASTRH + 2 * BK * BSTR) * 2 + 16 * BSTR * 4)

__device__ __forceinline__ void gemm_body(
    const __half* __restrict__ A, const __half* __restrict__ Bm,
    const float* __restrict__ bias, float* __restrict__ Cout,
    int M, int N, int K)
{
    extern __shared__ char smraw[];
    __half* As = (__half*)smraw;                       // 2 x BM x ASTRH
    __half* Bs = As + 2 * BM * ASTRH;                  // 2 x BK x BSTR
    float* biasT = (float*)(Bs + 2 * BK * BSTR);       // 16 x BSTR fp32

    const int tid = threadIdx.x;
    const int m0 = blockIdx.y * BM;
    const int n0 = blockIdx.x * BN;

    for (int i = tid; i < 16 * BN; i += 256) {
        int rr = i >> 7, cc = i & 127;
        biasT[rr * BSTR + cc] = bias[n0 + cc];
    }
    __syncthreads();

    const int w  = tid >> 5;
    const int wm = w >> 2;
    const int wn = w & 3;

    wmma::fragment<wmma::accumulator, 16, 16, 16, float> acc[4][2];
#pragma unroll
    for (int i = 0; i < 4; i++)
#pragma unroll
        for (int j = 0; j < 2; j++)
            wmma::load_matrix_sync(acc[i][j], &biasT[wn * 32 + j * 16], BSTR,
                                   wmma::mem_row_major);

    const int arow = tid >> 3, ac8 = (tid & 7) * 8;
    const int brow = tid >> 4, bc8 = (tid & 15) * 8;

    const int T = K / BK;

    {
        const __half* ag = &A[(size_t)(m0 + arow) * K + ac8];
        const __half* bg = &Bm[(size_t)brow * N + n0 + bc8];
#pragma unroll
        for (int p = 0; p < 4; p++)
            cpa16(&As[(arow + p * 32) * ASTRH + ac8], ag + (size_t)(p * 32) * K);
#pragma unroll
        for (int p = 0; p < 4; p++)
            cpa16(&Bs[(brow + p * 16) * BSTR + bc8], bg + (size_t)(p * 16) * N);
        cpa_commit();
    }

    for (int t = 0; t < T; t++) {
        if (t + 1 < T) {
            const int st = (t + 1) & 1;
            const int kt = (t + 1) * BK;
            const __half* ag = &A[(size_t)(m0 + arow) * K + kt + ac8];
            const __half* bg = &Bm[(size_t)(kt + brow) * N + n0 + bc8];
            __half* asd = &As[st * BM * ASTRH];
            __half* bsd = &Bs[st * BK * BSTR];
#pragma unroll
            for (int p = 0; p < 4; p++)
                cpa16(&asd[(arow + p * 32) * ASTRH + ac8], ag + (size_t)(p * 32) * K);
#pragma unroll
            for (int p = 0; p < 4; p++)
                cpa16(&bsd[(brow + p * 16) * BSTR + bc8], bg + (size_t)(p * 16) * N);
            cpa_commit();
            cpa_wait<1>();
        } else {
            cpa_wait<0>();
        }
        __syncthreads();

        const __half* asrc = &As[(t & 1) * BM * ASTRH];
        const __half* bsrc = &Bs[(t & 1) * BK * BSTR];

#pragma unroll
        for (int kk = 0; kk < BK; kk += 16) {
            wmma::fragment<wmma::matrix_a, 16, 16, 16, __half, wmma::row_major> af[4];
            wmma::fragment<wmma::matrix_b, 16, 16, 16, __half, wmma::row_major> bf[2];
#pragma unroll
            for (int i = 0; i < 4; i++)
                wmma::load_matrix_sync(af[i], &asrc[(wm * 64 + i * 16) * ASTRH + kk], ASTRH);
#pragma unroll
            for (int j = 0; j < 2; j++)
                wmma::load_matrix_sync(bf[j], &bsrc[kk * BSTR + wn * 32 + j * 16], BSTR);
#pragma unroll
            for (int i = 0; i < 4; i++)
#pragma unroll
                for (int j = 0; j < 2; j++)
                    wmma::mma_sync(acc[i][j], af[i], bf[j], acc[i][j]);
        }
        __syncthreads();
    }

#pragma unroll
    for (int i = 0; i < 4; i++)
#pragma unroll
        for (int j = 0; j < 2; j++)
            wmma::store_matrix_sync(
                Cout + (size_t)(m0 + wm * 64 + i * 16) * N + n0 + wn * 32 + j * 16,
                acc[i][j], N, wmma::mem_row_major);
}

__global__ __launch_bounds__(256, 2) void gemm_qkv_k(const float* __restrict__ bias)
{
    gemm_body(g_x, g_wqkv, bias, g_qkv, MROWS, C3, CC);
}

__global__ __launch_bounds__(256, 2) void gemm_proj_k(
    const float* __restrict__ bias, float* __restrict__ C)
{
    gemm_body(g_att, g_wproj, bias, C, MROWS, CC, CC);
}

// ---------------------------------------------------------------------------
// Fused attention, packed f32x2 FMA, 512 threads (16 warps) per CTA.
// Rel tables appended to K as extra "key" rows (coalesced rel dots).
// Softmax in log2 domain (scales folded), exps via packed f16x2 EX2 —
// halves MUFU ops, which are the CTA's dominant pipe cost.
// ---------------------------------------------------------------------------
#define KSTR 68
#define NWARP 16
#define NTHR (NWARP * 32)

#define SM_K   (288 * KSTR)          // K rows 0..195, pads, Rh 224.., Rw 256..
#define SM_V   (196 * KSTR)
#define SM_Q   (NWARP * 4 * KSTR)
#define SM_P   (NWARP * 4 * 200)
#define SM_REL (NWARP * 4 * 64)      // per warp: 4 rows x (32 relh + 32 relw)
#define ATTN_SMEM_FLOATS (SM_K + SM_V + SM_Q + SM_P + SM_REL)
#define ATTN_SMEM_BYTES (ATTN_SMEM_FLOATS * 4)

__global__ __launch_bounds__(NTHR) void attn_kernel(
    const float* __restrict__ rph, const float* __restrict__ rpw)
{
    extern __shared__ float sm[];
    float* kS  = sm;
    float* vS  = kS + SM_K;
    float* qsm = vS + SM_V;
    float* pbf = qsm + SM_Q;
    float* rlb = pbf + SM_P;

    const int tid  = threadIdx.x;
    const int head = blockIdx.x;
    const int b = head / NHEAD;
    const int h = head % NHEAD;

    const float* gbase = g_qkv + (size_t)b * HWSZ * C3 + h * HDIM;

    // Stage K, V
    for (int i = tid; i < HWSZ * HDIM; i += NTHR) {
        int j = i >> 6, d = i & 63;
        const float* p = gbase + (size_t)j * C3 + d;
        kS[j * KSTR + d] = p[768];
        vS[j * KSTR + d] = p[1536];
    }
    // Zero pad rows: 196..223, 251..255, 283..287
    for (int i = tid; i < 28 * KSTR; i += NTHR) kS[196 * KSTR + i] = 0.f;
    for (int i = tid; i < 5 * KSTR; i += NTHR) {
        kS[251 * KSTR + i] = 0.f;
        kS[283 * KSTR + i] = 0.f;
    }
    // Rel tables as extra key rows
    for (int i = tid; i < 27 * HDIM; i += NTHR) {
        int r = i >> 6, d = i & 63;
        kS[(224 + r) * KSTR + d] = rph[i];
        kS[(256 + r) * KSTR + d] = rpw[i];
    }
    __syncthreads();

    const int wid = tid >> 5, lane = tid & 31;
    float* qw = qsm + wid * 4 * KSTR;
    float* pw = pbf + wid * 800;
    float* rb = rlb + wid * 256;

    for (int g = wid; g < 49; g += NWARP) {
        const int r0 = g * 4;

        for (int i = lane; i < 4 * HDIM; i += 32) {
            int rr = i >> 6, d = i & 63;
            qw[rr * KSTR + d] = gbase[(size_t)(r0 + rr) * C3 + d];
        }
        __syncwarp();

        // QK^T main keys: packed along d
        u64 acc2[4][7];
#pragma unroll
        for (int rr = 0; rr < 4; rr++)
#pragma unroll
            for (int jj = 0; jj < 7; jj++) acc2[rr][jj] = 0ull;

#pragma unroll 4
        for (int d0 = 0; d0 < 64; d0 += 4) {
            ulonglong2 qv[4];
#pragma unroll
            for (int rr = 0; rr < 4; rr++)
                qv[rr] = *(const ulonglong2*)(qw + rr * KSTR + d0);
#pragma unroll
            for (int jj = 0; jj < 7; jj++) {
                int j = lane + jj * 32;  // pad rows (>=196) are zero
                ulonglong2 kv = *(const ulonglong2*)(kS + j * KSTR + d0);
#pragma unroll
                for (int rr = 0; rr < 4; rr++) {
                    acc2[rr][jj] = fma2(kv.x, qv[rr].x, acc2[rr][jj]);
                    acc2[rr][jj] = fma2(kv.y, qv[rr].y, acc2[rr][jj]);
                }
            }
        }

        // Rel-pos dots, stored pre-scaled by log2(e)
        {
            u64 ar[4][2];
#pragma unroll
            for (int rr = 0; rr < 4; rr++) { ar[rr][0] = 0ull; ar[rr][1] = 0ull; }
#pragma unroll 4
            for (int d0 = 0; d0 < 64; d0 += 4) {
                ulonglong2 qv[4];
#pragma unroll
                for (int rr = 0; rr < 4; rr++)
                    qv[rr] = *(const ulonglong2*)(qw + rr * KSTR + d0);
                ulonglong2 hv = *(const ulonglong2*)(kS + (224 + lane) * KSTR + d0);
                ulonglong2 wv = *(const ulonglong2*)(kS + (256 + lane) * KSTR + d0);
#pragma unroll
                for (int rr = 0; rr < 4; rr++) {
                    ar[rr][0] = fma2(hv.x, qv[rr].x, ar[rr][0]);
                    ar[rr][0] = fma2(hv.y, qv[rr].y, ar[rr][0]);
                    ar[rr][1] = fma2(wv.x, qv[rr].x, ar[rr][1]);
                    ar[rr][1] = fma2(wv.y, qv[rr].y, ar[rr][1]);
                }
            }
            if (lane < 27) {
#pragma unroll
                for (int rr = 0; rr < 4; rr++) {
                    rb[rr * 64 + lane]      = hsum2(ar[rr][0]) * LOG2E;
                    rb[rr * 64 + 32 + lane] = hsum2(ar[rr][1]) * LOG2E;
                }
            }
        }
        __syncwarp();

        // softmax in log2 domain; exps via packed f16x2 EX2
        float inv[4];
#pragma unroll
        for (int rr = 0; rr < 4; rr++) {
            const int r = r0 + rr;
            const int hq = r / 14, wq = r % 14;
            const float* rbh = rb + rr * 64 + hq + 13;       // index - j/14
            const float* rbw = rb + rr * 64 + 32 + wq + 13;  // index - j%14
            float s[7];
#pragma unroll
            for (int jj = 0; jj < 7; jj++) {
                int j = lane + jj * 32;
                s[jj] = (j < HWSZ)
                      ? hsum2(acc2[rr][jj]) * QK_SCALE_LOG2
                          + rbh[-(j / 14)] + rbw[-(j % 14)]
                      : -30.0f;  // f16 exp2 flushes to 0
            }
            float2 e01 = exp2_2(s[0], s[1]);
            float2 e23 = exp2_2(s[2], s[3]);
            float2 e45 = exp2_2(s[4], s[5]);
            float2 e66 = exp2_2(s[6], s[6]);
            float e[7] = {e01.x, e01.y, e23.x, e23.y, e45.x, e45.y, e66.x};
            float lsum = 0.f;
#pragma unroll
            for (int jj = 0; jj < 7; jj++) {
                int j = lane + jj * 32;
                lsum += e[jj];
                if (j < HWSZ) pw[rr * 200 + j] = e[jj];
            }
#pragma unroll
            for (int o = 16; o > 0; o >>= 1)
                lsum += __shfl_xor_sync(0xffffffffu, lsum, o);
            inv[rr] = 1.f / lsum;
        }
        __syncwarp();

        // P @ V: packed along key pairs
        u64 o20[4] = {0ull, 0ull, 0ull, 0ull};
        u64 o21[4] = {0ull, 0ull, 0ull, 0ull};
#pragma unroll 2
        for (int j = 0; j < HWSZ; j += 2) {
            float2 va = *(const float2*)(vS + j * KSTR + 2 * lane);
            float2 vb = *(const float2*)(vS + (j + 1) * KSTR + 2 * lane);
            u64 vx = pack2(va.x, vb.x);
            u64 vy = pack2(va.y, vb.y);
#pragma unroll
            for (int rr = 0; rr < 4; rr++) {
                u64 pp = *(const u64*)(pw + rr * 200 + j);
                o20[rr] = fma2(pp, vx, o20[rr]);
                o21[rr] = fma2(pp, vy, o21[rr]);
            }
        }

        __half* gout = g_att + ((size_t)b * HWSZ + r0) * CC + h * HDIM;
#pragma unroll
        for (int rr = 0; rr < 4; rr++) {
            __half2 res = __floats2half2_rn(hsum2(o20[rr]) * inv[rr],
                                            hsum2(o21[rr]) * inv[rr]);
            *(__half2*)(gout + (size_t)rr * CC + 2 * lane) = res;
        }
        __syncwarp();
    }
}

// ---------------------------------------------------------------------------
extern "C" void kernel_launch(void* const* d_in, const int* in_sizes, int n_in,
                              void* d_out, int out_size)
{
    const float* x      = (const float*)d_in[0]; // (25088, 768)
    const float* w_qkv  = (const float*)d_in[1]; // (768, 2304)
    const float* b_qkv  = (const float*)d_in[2]; // (2304,)
    const float* rph    = (const float*)d_in[3]; // (27, 64)
    const float* rpw    = (const float*)d_in[4]; // (27, 64)
    const float* w_proj = (const float*)d_in[5]; // (768, 768)
    const float* b_proj = (const float*)d_in[6]; // (768,)
    float* out = (float*)d_out;                  // (25088, 768)

    __half *d_x, *d_wqkv, *d_wproj;
    cudaGetSymbolAddress((void**)&d_x, g_x);
    cudaGetSymbolAddress((void**)&d_wqkv, g_wqkv);
    cudaGetSymbolAddress((void**)&d_wproj, g_wproj);

    cudaFuncSetAttribute(gemm_qkv_k,
                         cudaFuncAttributeMaxDynamicSharedMemorySize,
                         GEMM_SMEM_BYTES);
    cudaFuncSetAttribute(gemm_proj_k,
                         cudaFuncAttributeMaxDynamicSharedMemorySize,
                         GEMM_SMEM_BYTES);
    cudaFuncSetAttribute(attn_kernel,
                         cudaFuncAttributeMaxDynamicSharedMemorySize,
                         ATTN_SMEM_BYTES);

    // Convert GEMM inputs to fp16
    {
        int n4 = MROWS * CC / 4;
        to_half_kernel<<<(n4 + 255) / 256, 256>>>(x, d_x, n4);
        n4 = CC * C3 / 4;
        to_half_kernel<<<(n4 + 255) / 256, 256>>>(w_qkv, d_wqkv, n4);
        n4 = CC * CC / 4;
        to_half_kernel<<<(n4 + 255) / 256, 256>>>(w_proj, d_wproj, n4);
    }

    dim3 g1(C3 / BN, MROWS / BM);   // 18 x 196
    gemm_qkv_k<<<g1, 256, GEMM_SMEM_BYTES>>>(b_qkv);

    attn_kernel<<<NHEADS_TOTAL, NTHR, ATTN_SMEM_BYTES>>>(rph, rpw);

    dim3 g2(CC / BN, MROWS / BM);   // 6 x 196
    gemm_proj_k<<<g2, 256, GEMM_SMEM_BYTES>>>(b_proj, out);
}

// round 11
// speedup vs baseline: 1.6558x; 1.6241x over previous
#include <cuda_runtime.h>
#include <cuda_fp16.h>
#include <mma.h>
#include <cstddef>
#include <cstdint>

using namespace nvcuda;

// Problem constants
#define BATCH 128
#define HH 14
#define WW 14
#define CC 768
#define NHEAD 12
#define HDIM 64
#define HWSZ 196          // 14*14
#define C3 2304           // 3*C
#define MROWS 25088       // BATCH*HWSZ
#define NHEADS_TOTAL 1536 // BATCH*NHEAD

#define LOG2E 1.442695040888963f

// Scratch buffers (device globals: no allocation allowed)
__device__ __half g_qkv[(size_t)MROWS * C3];  // qkv GEMM out (fp16)
__device__ __half g_att[(size_t)MROWS * CC];  // attention out (fp16)
__device__ __half g_x[(size_t)MROWS * CC];    // x (fp16)
__device__ __half g_wqkv[(size_t)CC * C3];    // w_qkv (fp16)
__device__ __half g_wproj[(size_t)CC * CC];   // w_proj (fp16)

// ---------------------------------------------------------------------------
// helpers
// ---------------------------------------------------------------------------
__global__ void to_half_kernel(const float* __restrict__ in,
                               __half* __restrict__ out, int n4)
{
    int i = blockIdx.x * blockDim.x + threadIdx.x;
    if (i < n4) {
        float4 v = ((const float4*)in)[i];
        __half2 a = __floats2half2_rn(v.x, v.y);
        __half2 b = __floats2half2_rn(v.z, v.w);
        uint2 pk;
        pk.x = *(uint32_t*)&a;
        pk.y = *(uint32_t*)&b;
        ((uint2*)out)[i] = pk;
    }
}

// Packed 2^x for two fp32 args via f16x2 MUFU (1 EX2 for 2 values).
__device__ __forceinline__ float2 exp2_2(float a, float b) {
    uint32_t h, e;
    asm("cvt.rn.f16x2.f32 %0, %1, %2;" : "=r"(h) : "f"(b), "f"(a)); // hi=b, lo=a
    asm("ex2.approx.f16x2 %0, %1;" : "=r"(e) : "r"(h));
    float2 r;
    asm("{.reg .f16 lo, hi;\n\t"
        "mov.b32 {lo, hi}, %2;\n\t"
        "cvt.f32.f16 %0, lo;\n\t"
        "cvt.f32.f16 %1, hi;}"
        : "=f"(r.x), "=f"(r.y) : "r"(e));
    return r;
}

__device__ __forceinline__ void cpa16(void* s, const void* g) {
    uint32_t sa = (uint32_t)__cvta_generic_to_shared(s);
    asm volatile("cp.async.cg.shared.global [%0], [%1], 16;\n" ::"r"(sa), "l"(g));
}
__device__ __forceinline__ void cpa_commit() {
    asm volatile("cp.async.commit_group;\n" ::);
}
template <int N>
__device__ __forceinline__ void cpa_wait() {
    asm volatile("cp.async.wait_group %0;\n" ::"n"(N));
}

// ---------------------------------------------------------------------------
// Pipelined fp16 GEMM: C = A(MxK,f16) @ B(KxN,f16) + bias(fp32)
// BM=BN=128, BK=64, wmma m16n16k16, 2-stage cp.async, 256 thr, 2 CTA/SM.
// HALF_OUT: store fp16 via per-warp smem staging; else fp32 direct.
// ---------------------------------------------------------------------------
#define BM 128
#define BN 128
#define BK 64
#define BSTR 136   // halves per B row: 128 + 8 pad
#define ASTRH 72   // halves per A row: 64 + 8 pad

#define GEMM_SMEM_BYTES ((2 * BM * ASTRH + 2 * BK * BSTR) * 2 + 16 * BSTR * 4 + 8 * 320 * 4)

template <bool HALF_OUT>
__device__ __forceinline__ void gemm_body(
    const __half* __restrict__ A, const __half* __restrict__ Bm,
    const float* __restrict__ bias, void* __restrict__ Cout,
    int M, int N, int K)
{
    extern __shared__ char smraw[];
    __half* As = (__half*)smraw;                       // 2 x BM x ASTRH
    __half* Bs = As + 2 * BM * ASTRH;                  // 2 x BK x BSTR
    float* biasT = (float*)(Bs + 2 * BK * BSTR);       // 16 x BSTR fp32
    float* scr = biasT + 16 * BSTR;                    // 8 warps x 16x20 fp32

    const int tid = threadIdx.x;
    const int m0 = blockIdx.y * BM;
    const int n0 = blockIdx.x * BN;

    for (int i = tid; i < 16 * BN; i += 256) {
        int rr = i >> 7, cc = i & 127;
        biasT[rr * BSTR + cc] = bias[n0 + cc];
    }
    __syncthreads();

    const int w  = tid >> 5;
    const int lane = tid & 31;
    const int wm = w >> 2;
    const int wn = w & 3;

    wmma::fragment<wmma::accumulator, 16, 16, 16, float> acc[4][2];
#pragma unroll
    for (int i = 0; i < 4; i++)
#pragma unroll
        for (int j = 0; j < 2; j++)
            wmma::load_matrix_sync(acc[i][j], &biasT[wn * 32 + j * 16], BSTR,
                                   wmma::mem_row_major);

    const int arow = tid >> 3, ac8 = (tid & 7) * 8;
    const int brow = tid >> 4, bc8 = (tid & 15) * 8;

    const int T = K / BK;

    {
        const __half* ag = &A[(size_t)(m0 + arow) * K + ac8];
        const __half* bg = &Bm[(size_t)brow * N + n0 + bc8];
#pragma unroll
        for (int p = 0; p < 4; p++)
            cpa16(&As[(arow + p * 32) * ASTRH + ac8], ag + (size_t)(p * 32) * K);
#pragma unroll
        for (int p = 0; p < 4; p++)
            cpa16(&Bs[(brow + p * 16) * BSTR + bc8], bg + (size_t)(p * 16) * N);
        cpa_commit();
    }

    for (int t = 0; t < T; t++) {
        if (t + 1 < T) {
            const int st = (t + 1) & 1;
            const int kt = (t + 1) * BK;
            const __half* ag = &A[(size_t)(m0 + arow) * K + kt + ac8];
            const __half* bg = &Bm[(size_t)(kt + brow) * N + n0 + bc8];
            __half* asd = &As[st * BM * ASTRH];
            __half* bsd = &Bs[st * BK * BSTR];
#pragma unroll
            for (int p = 0; p < 4; p++)
                cpa16(&asd[(arow + p * 32) * ASTRH + ac8], ag + (size_t)(p * 32) * K);
#pragma unroll
            for (int p = 0; p < 4; p++)
                cpa16(&bsd[(brow + p * 16) * BSTR + bc8], bg + (size_t)(p * 16) * N);
            cpa_commit();
            cpa_wait<1>();
        } else {
            cpa_wait<0>();
        }
        __syncthreads();

        const __half* asrc = &As[(t & 1) * BM * ASTRH];
        const __half* bsrc = &Bs[(t & 1) * BK * BSTR];

#pragma unroll
        for (int kk = 0; kk < BK; kk += 16) {
            wmma::fragment<wmma::matrix_a, 16, 16, 16, __half, wmma::row_major> af[4];
            wmma::fragment<wmma::matrix_b, 16, 16, 16, __half, wmma::row_major> bf[2];
#pragma unroll
            for (int i = 0; i < 4; i++)
                wmma::load_matrix_sync(af[i], &asrc[(wm * 64 + i * 16) * ASTRH + kk], ASTRH);
#pragma unroll
            for (int j = 0; j < 2; j++)
                wmma::load_matrix_sync(bf[j], &bsrc[kk * BSTR + wn * 32 + j * 16], BSTR);
#pragma unroll
            for (int i = 0; i < 4; i++)
#pragma unroll
                for (int j = 0; j < 2; j++)
                    wmma::mma_sync(acc[i][j], af[i], bf[j], acc[i][j]);
        }
        __syncthreads();
    }

    if (HALF_OUT) {
        __half* Ch = (__half*)Cout;
        float* myscr = scr + w * 320;
        const int lr = lane >> 1, lc = (lane & 1) * 4;
#pragma unroll
        for (int i = 0; i < 4; i++)
#pragma unroll
            for (int j = 0; j < 2; j++) {
                wmma::store_matrix_sync(myscr, acc[i][j], 20, wmma::mem_row_major);
                __syncwarp();
#pragma unroll
                for (int k = 0; k < 4; k++) {
                    int c2 = lc + k;
                    __half2 v = __floats2half2_rn(myscr[lr * 20 + c2 * 2],
                                                  myscr[lr * 20 + c2 * 2 + 1]);
                    *(__half2*)(Ch + (size_t)(m0 + wm * 64 + i * 16 + lr) * N
                                + n0 + wn * 32 + j * 16 + c2 * 2) = v;
                }
                __syncwarp();
            }
    } else {
#pragma unroll
        for (int i = 0; i < 4; i++)
#pragma unroll
            for (int j = 0; j < 2; j++)
                wmma::store_matrix_sync(
                    (float*)Cout + (size_t)(m0 + wm * 64 + i * 16) * N
                        + n0 + wn * 32 + j * 16,
                    acc[i][j], N, wmma::mem_row_major);
    }
}

__global__ __launch_bounds__(256, 2) void gemm_qkv_k(const float* __restrict__ bias)
{
    gemm_body<true>(g_x, g_wqkv, bias, g_qkv, MROWS, C3, CC);
}

__global__ __launch_bounds__(256, 2) void gemm_proj_k(
    const float* __restrict__ bias, float* __restrict__ C)
{
    gemm_body<false>(g_att, g_wproj, bias, C, MROWS, CC, CC);
}

// ---------------------------------------------------------------------------
// Tensorized fp16 attention: one CTA per (batch, head), 512 threads (16 warps).
// K (rows 0..195) + rel tables (rows 224..250 Rh, 256..282 Rw) resident in
// fp16 smem; V resident; queries in 4 blocks of 64 rows.
// Per block: QK^T (4x18 wmma tiles) -> log2-softmax (packed f16 EX2,
// normalization folded into fp16 P) -> PV (4x4 wmma tiles, k=224) -> fp16 out.
// ---------------------------------------------------------------------------
#define AKSTR 72      // halves per K/V/Q row (64 + 8 pad)
#define SSTRF 296     // fp32 S row stride
#define PSTR 232      // halves per P row

#define ASM_K (288 * AKSTR)
#define ASM_V (224 * AKSTR)
#define ASM_Q (64 * AKSTR)
#define ASM_P (64 * PSTR)
#define ASM_S (64 * SSTRF)
#define ATTN_SMEM_BYTES ((ASM_K + ASM_V + ASM_Q + ASM_P) * 2 + ASM_S * 4)

__global__ __launch_bounds__(512) void attn_kernel(
    const float* __restrict__ rph, const float* __restrict__ rpw)
{
    extern __shared__ char smraw[];
    __half* kS = (__half*)smraw;
    __half* vS = kS + ASM_K;
    __half* qS = vS + ASM_V;
    __half* pS = qS + ASM_Q;
    float*  sS = (float*)(pS + ASM_P);

    const int tid = threadIdx.x;
    const int wid = tid >> 5, lane = tid & 31;
    const int head = blockIdx.x;
    const int b = head / NHEAD;
    const int h = head % NHEAD;

    const __half* gbase = g_qkv + (size_t)b * HWSZ * C3 + h * HDIM;

    // Zero pad rows: kS 196..223, 251..255, 283..287; vS 196..223 (uint4 = 8 halves)
    {
        const uint4 z = make_uint4(0, 0, 0, 0);
        for (int i = tid; i < 28 * 9; i += 512) ((uint4*)(kS + 196 * AKSTR))[i] = z;
        for (int i = tid; i < 5 * 9; i += 512) {
            ((uint4*)(kS + 251 * AKSTR))[i] = z;
            ((uint4*)(kS + 283 * AKSTR))[i] = z;
        }
        for (int i = tid; i < 28 * 9; i += 512) ((uint4*)(vS + 196 * AKSTR))[i] = z;
    }
    // Stage K, V via cp.async (fp16 source)
    for (int i = tid; i < HWSZ * 8; i += 512) {
        int j = i >> 3, seg = (i & 7) * 8;
        cpa16(kS + j * AKSTR + seg, gbase + (size_t)j * C3 + 768 + seg);
        cpa16(vS + j * AKSTR + seg, gbase + (size_t)j * C3 + 1536 + seg);
    }
    cpa_commit();
    // Rel tables (fp32 -> fp16) as extra key rows
    for (int i = tid; i < 27 * HDIM; i += 512) {
        int r = i >> 6, d = i & 63;
        kS[(224 + r) * AKSTR + d] = __float2half(rph[i]);
        kS[(256 + r) * AKSTR + d] = __float2half(rpw[i]);
    }
    cpa_wait<0>();
    __syncthreads();

    for (int blk = 0; blk < 4; blk++) {
        const int r0 = blk * 64;

        // --- Stage Q block (64 x 64 fp16), zero invalid rows ---
        for (int i = tid; i < 64 * 8; i += 512) {
            int r = i >> 3, seg = (i & 7) * 8;
            uint4 v = make_uint4(0, 0, 0, 0);
            if (r0 + r < HWSZ)
                v = *(const uint4*)(gbase + (size_t)(r0 + r) * C3 + seg);
            *(uint4*)(qS + r * AKSTR + seg) = v;
        }
        __syncthreads();

        // --- QK^T (+rel cols): 4x18 tiles of 16x16, k=64 ---
        for (int t = wid; t < 72; t += 16) {
            const int mt = t / 18, nt = t % 18;
            wmma::fragment<wmma::accumulator, 16, 16, 16, float> acc;
            wmma::fill_fragment(acc, 0.f);
#pragma unroll
            for (int ks = 0; ks < 4; ks++) {
                wmma::fragment<wmma::matrix_a, 16, 16, 16, __half, wmma::row_major> af;
                wmma::fragment<wmma::matrix_b, 16, 16, 16, __half, wmma::col_major> bf;
                wmma::load_matrix_sync(af, qS + mt * 16 * AKSTR + ks * 16, AKSTR);
                wmma::load_matrix_sync(bf, kS + nt * 16 * AKSTR + ks * 16, AKSTR);
                wmma::mma_sync(acc, af, bf, acc);
            }
            wmma::store_matrix_sync(sS + mt * 16 * SSTRF + nt * 16, acc, SSTRF,
                                    wmma::mem_row_major);
        }
        __syncthreads();

        // --- Softmax (8 threads/row, 28 cols each), P = e/sum in fp16 ---
        {
            const int r = tid >> 3, sub = tid & 7;
            const int qr = r0 + r;
            const int qv = (qr < HWSZ) ? qr : 0;
            const int hq = qv / 14, wq = qv % 14;
            const float* srow = sS + r * SSTRF;
            float e[28];
            float lsum = 0.f;
#pragma unroll
            for (int i = 0; i < 28; i += 2) {
                float s01[2];
#pragma unroll
                for (int u = 0; u < 2; u++) {
                    int j = sub + (i + u) * 8;
                    if (j < HWSZ) {
                        int i1 = hq - j / 14 + 13;
                        int i2 = wq - j % 14 + 13;
                        s01[u] = (srow[j] * 0.125f + srow[224 + i1] + srow[256 + i2])
                                 * LOG2E;
                    } else {
                        s01[u] = -30.0f;  // exp2 -> 0 in f16
                    }
                }
                float2 ee = exp2_2(s01[0], s01[1]);
                e[i] = ee.x;
                e[i + 1] = ee.y;
                lsum += ee.x + ee.y;
            }
#pragma unroll
            for (int o = 4; o > 0; o >>= 1)
                lsum += __shfl_xor_sync(0xffffffffu, lsum, o);
            const float inv = 1.f / lsum;
            __half* prow = pS + r * PSTR;
#pragma unroll
            for (int i = 0; i < 28; i++)
                prow[sub + i * 8] = __float2half(e[i] * inv);
        }
        __syncthreads();

        // --- PV: 4x4 tiles of 16x16, k=224 (14 steps); O -> sS ---
        {
            const int mt = wid >> 2, nt = wid & 3;
            wmma::fragment<wmma::accumulator, 16, 16, 16, float> acc;
            wmma::fill_fragment(acc, 0.f);
#pragma unroll
            for (int ks = 0; ks < 14; ks++) {
                wmma::fragment<wmma::matrix_a, 16, 16, 16, __half, wmma::row_major> af;
                wmma::fragment<wmma::matrix_b, 16, 16, 16, __half, wmma::row_major> bf;
                wmma::load_matrix_sync(af, pS + mt * 16 * PSTR + ks * 16, PSTR);
                wmma::load_matrix_sync(bf, vS + ks * 16 * AKSTR + nt * 16, AKSTR);
                wmma::mma_sync(acc, af, bf, acc);
            }
            wmma::store_matrix_sync(sS + mt * 16 * SSTRF + nt * 16, acc, SSTRF,
                                    wmma::mem_row_major);
        }
        __syncthreads();

        // --- Store valid O rows (fp16) ---
        {
            const int nv = (HWSZ - r0 < 64) ? (HWSZ - r0) : 64;
            __half* gout = g_att + ((size_t)b * HWSZ + r0) * CC + h * HDIM;
            for (int idx = tid; idx < 64 * 32; idx += 512) {
                int r = idx >> 5, c2 = idx & 31;
                if (r < nv) {
                    __half2 v = __floats2half2_rn(sS[r * SSTRF + c2 * 2],
                                                  sS[r * SSTRF + c2 * 2 + 1]);
                    *(__half2*)(gout + (size_t)r * CC + c2 * 2) = v;
                }
            }
        }
        __syncthreads();
    }
}

// ---------------------------------------------------------------------------
extern "C" void kernel_launch(void* const* d_in, const int* in_sizes, int n_in,
                              void* d_out, int out_size)
{
    const float* x      = (const float*)d_in[0]; // (25088, 768)
    const float* w_qkv  = (const float*)d_in[1]; // (768, 2304)
    const float* b_qkv  = (const float*)d_in[2]; // (2304,)
    const float* rph    = (const float*)d_in[3]; // (27, 64)
    const float* rpw    = (const float*)d_in[4]; // (27, 64)
    const float* w_proj = (const float*)d_in[5]; // (768, 768)
    const float* b_proj = (const float*)d_in[6]; // (768,)
    float* out = (float*)d_out;                  // (25088, 768)

    __half *d_x, *d_wqkv, *d_wproj;
    cudaGetSymbolAddress((void**)&d_x, g_x);
    cudaGetSymbolAddress((void**)&d_wqkv, g_wqkv);
    cudaGetSymbolAddress((void**)&d_wproj, g_wproj);

    cudaFuncSetAttribute(gemm_qkv_k,
                         cudaFuncAttributeMaxDynamicSharedMemorySize,
                         GEMM_SMEM_BYTES);
    cudaFuncSetAttribute(gemm_proj_k,
                         cudaFuncAttributeMaxDynamicSharedMemorySize,
                         GEMM_SMEM_BYTES);
    cudaFuncSetAttribute(attn_kernel,
                         cudaFuncAttributeMaxDynamicSharedMemorySize,
                         ATTN_SMEM_BYTES);

    // Convert GEMM inputs to fp16
    {
        int n4 = MROWS * CC / 4;
        to_half_kernel<<<(n4 + 255) / 256, 256>>>(x, d_x, n4);
        n4 = CC * C3 / 4;
        to_half_kernel<<<(n4 + 255) / 256, 256>>>(w_qkv, d_wqkv, n4);
        n4 = CC * CC / 4;
        to_half_kernel<<<(n4 + 255) / 256, 256>>>(w_proj, d_wproj, n4);
    }

    dim3 g1(C3 / BN, MROWS / BM);   // 18 x 196
    gemm_qkv_k<<<g1, 256, GEMM_SMEM_BYTES>>>(b_qkv);

    attn_kernel<<<NHEADS_TOTAL, 512, ATTN_SMEM_BYTES>>>(rph, rpw);

    dim3 g2(CC / BN, MROWS / BM);   // 6 x 196
    gemm_proj_k<<<g2, 256, GEMM_SMEM_BYTES>>>(b_proj, out);
}